// round 13
// baseline (speedup 1.0000x reference)
#include <cuda_runtime.h>
#include <cstdint>

// Problem constants (fixed shapes)
#define BXN 128
#define BYN 128
#define TN  1024
#define DN  64
#define NSTEPS 1023
#define CL  16      // t-steps per chunk
#define NC  64      // chunks
#define TI  64
#define TJ  64
#define NTHREADS 128
#define PAD 68      // smem row stride (floats), keeps float4 alignment + no conflicts

__device__ float g_Cprod[NC * BXN * BYN];
__device__ float g_Pexc [NC * BXN * BYN];

__device__ __forceinline__ void cp_async16(uint32_t dst, const float* src) {
    asm volatile("cp.async.ca.shared.global [%0], [%1], 16;\n" :: "r"(dst), "l"(src));
}
__device__ __forceinline__ void cp_commit() {
    asm volatile("cp.async.commit_group;\n");
}
__device__ __forceinline__ void cp_wait0() {
    asm volatile("cp.async.wait_group 0;\n");
}

// ---------------------------------------------------------------------------
// K1: per-chunk local cumulative products.
// Grid (4, NC), 128 threads (all 4 SMSPs), 64x64 tile, 8x4 micro-tile.
// Row data moves gmem -> smem COALESCED via cp.async (4 wavefronts per warp
// instr instead of 32 for the old per-thread-row LDGs -- this was the
// bottleneck in R1-R11). Thread tid then diffs its own row (rawN[tid]) against
// register cur[16] and writes transposed increments to dxs/dys.
// ---------------------------------------------------------------------------
__launch_bounds__(NTHREADS, 2)
__global__ void k1_chunk(const float* __restrict__ X,
                         const float* __restrict__ Y,
                         float* __restrict__ out)
{
    const int i0    = (blockIdx.x & 1) * TI;
    const int j0    = (blockIdx.x >> 1) * TJ;
    const int tbase = blockIdx.y * CL;

    __shared__ float rawN[128 * PAD];        // raw rows of one time point (34.8KB)
    __shared__ float dxs[DN][PAD];           // transposed increments [d][i]
    __shared__ float dys[DN][PAD];           // [d][j]
    __shared__ float staging[2][TI * TJ];    // 2 t-slots (32KB)

    const int tid  = threadIdx.x;
    const int tx   = tid & 15;               // j-group (4 j's)
    const int ty   = tid >> 4;               // i-group (8 i's)
    const int rh   = tid >> 4;               // loader row-offset within 8-row group
    const int quad = tid & 15;               // d-quad

    const float STEP = 1.0f / 1023.0f;       // jnp.linspace delta in fp32

    // coalesced loader bases: q=0..7 -> X rows i0+q*8+rh ; q=8..15 -> Y rows
    const float* gx = X + (size_t)(i0 + rh) * TN * DN + quad * 4;
    const float* gy = Y + (size_t)(j0 + rh) * TN * DN + quad * 4;
    const size_t RSTRIDE = (size_t)8 * TN * DN;   // 8 rows in elements
    const uint32_t sbase = (uint32_t)__cvta_generic_to_shared(rawN)
                         + (uint32_t)(rh * PAD + quad * 4) * 4u;

    // issue one full time-slice (128 rows x 64 d) coalesced into rawN
    auto load_slice = [&](int tt) {
        const size_t off = (size_t)tt * DN;
#pragma unroll
        for (int q = 0; q < 8; q++)
            cp_async16(sbase + (uint32_t)(q * 8 * PAD * 4), gx + q * RSTRIDE + off);
#pragma unroll
        for (int q = 0; q < 8; q++)
            cp_async16(sbase + (uint32_t)((q + 8) * 8 * PAD * 4), gy + q * RSTRIDE + off);
        cp_commit();
    };

    // transposer destination: thread tid owns raw row tid
    float* dst = (tid < 64) ? &dxs[0][0] : &dys[0][0];
    const int r = tid & 63;

    float4 cur[16];

    // ---- prologue ----
    load_slice(tbase + 1);
    cp_wait0();
    __syncthreads();
#pragma unroll
    for (int q = 0; q < 16; q++)
        cur[q] = *(const float4*)&rawN[tid * PAD + q * 4];
    __syncthreads();

    load_slice(tbase);
    cp_wait0();
    __syncthreads();
#pragma unroll
    for (int q = 0; q < 16; q++) {
        float4 o = *(const float4*)&rawN[tid * PAD + q * 4];
        const int d0 = q * 4;
        dst[(d0 + 0) * PAD + r] = cur[q].x - o.x;
        dst[(d0 + 1) * PAD + r] = cur[q].y - o.y;
        dst[(d0 + 2) * PAD + r] = cur[q].z - o.z;
        dst[(d0 + 3) * PAD + r] = cur[q].w - o.w;
    }
    __syncthreads();

    float K[8][4];
#pragma unroll
    for (int a = 0; a < 8; a++)
#pragma unroll
        for (int b = 0; b < 4; b++) K[a][b] = 1.0f;

#pragma unroll 1
    for (int k = 0; k < CL; k++) {
        const int  s    = tbase + k;
        const bool more = (k + 1 < CL) && (s + 1 < NSTEPS);

        // ---- stage current K (local value of out[t=s]) ----
#pragma unroll
        for (int a = 0; a < 8; a++) {
            float4 v = make_float4(K[a][0], K[a][1], K[a][2], K[a][3]);
            *(float4*)&staging[k & 1][(ty * 8 + a) * TJ + tx * 4] = v;
        }

        // ---- kick off coalesced load of rows(s+2); lands during FMA ----
        if (more) load_slice(s + 2);

        // ---- dot + scan update ----
        if (s < NSTEPS) {
            const float t1  = (s + 1 == NSTEPS) ? 1.0f : (float)(s + 1) * STEP;
            const float t0  = (float)s * STEP;
            const float inv = 1.0f / (t1 - t0);

            float acc[8][4];
#pragma unroll
            for (int a = 0; a < 8; a++)
#pragma unroll
                for (int b = 0; b < 4; b++) acc[a][b] = 0.0f;

#pragma unroll 8
            for (int d = 0; d < DN; d++) {
                const float4 yb  = *(const float4*)&dys[d][tx * 4];
                const float4 xa0 = *(const float4*)&dxs[d][ty * 8];
                const float4 xa1 = *(const float4*)&dxs[d][ty * 8 + 4];
                acc[0][0] = fmaf(xa0.x, yb.x, acc[0][0]);
                acc[0][1] = fmaf(xa0.x, yb.y, acc[0][1]);
                acc[0][2] = fmaf(xa0.x, yb.z, acc[0][2]);
                acc[0][3] = fmaf(xa0.x, yb.w, acc[0][3]);
                acc[1][0] = fmaf(xa0.y, yb.x, acc[1][0]);
                acc[1][1] = fmaf(xa0.y, yb.y, acc[1][1]);
                acc[1][2] = fmaf(xa0.y, yb.z, acc[1][2]);
                acc[1][3] = fmaf(xa0.y, yb.w, acc[1][3]);
                acc[2][0] = fmaf(xa0.z, yb.x, acc[2][0]);
                acc[2][1] = fmaf(xa0.z, yb.y, acc[2][1]);
                acc[2][2] = fmaf(xa0.z, yb.z, acc[2][2]);
                acc[2][3] = fmaf(xa0.z, yb.w, acc[2][3]);
                acc[3][0] = fmaf(xa0.w, yb.x, acc[3][0]);
                acc[3][1] = fmaf(xa0.w, yb.y, acc[3][1]);
                acc[3][2] = fmaf(xa0.w, yb.z, acc[3][2]);
                acc[3][3] = fmaf(xa0.w, yb.w, acc[3][3]);
                acc[4][0] = fmaf(xa1.x, yb.x, acc[4][0]);
                acc[4][1] = fmaf(xa1.x, yb.y, acc[4][1]);
                acc[4][2] = fmaf(xa1.x, yb.z, acc[4][2]);
                acc[4][3] = fmaf(xa1.x, yb.w, acc[4][3]);
                acc[5][0] = fmaf(xa1.y, yb.x, acc[5][0]);
                acc[5][1] = fmaf(xa1.y, yb.y, acc[5][1]);
                acc[5][2] = fmaf(xa1.y, yb.z, acc[5][2]);
                acc[5][3] = fmaf(xa1.y, yb.w, acc[5][3]);
                acc[6][0] = fmaf(xa1.z, yb.x, acc[6][0]);
                acc[6][1] = fmaf(xa1.z, yb.y, acc[6][1]);
                acc[6][2] = fmaf(xa1.z, yb.z, acc[6][2]);
                acc[6][3] = fmaf(xa1.z, yb.w, acc[6][3]);
                acc[7][0] = fmaf(xa1.w, yb.x, acc[7][0]);
                acc[7][1] = fmaf(xa1.w, yb.y, acc[7][1]);
                acc[7][2] = fmaf(xa1.w, yb.z, acc[7][2]);
                acc[7][3] = fmaf(xa1.w, yb.w, acc[7][3]);
            }

#pragma unroll
            for (int a = 0; a < 8; a++)
#pragma unroll
                for (int b = 0; b < 4; b++)
                    K[a][b] *= fmaf(acc[a][b], inv, 1.0f);
        }

        if (more) cp_wait0();   // own copies landed; barrier publishes all
        __syncthreads();        // b1: dxs readers done; staging + rawN visible

        // ---- flush 2 staged t-slices as contiguous float2 runs ----
        if (k & 1) {
            const int tflush = s - 1;
#pragma unroll
            for (int w = 0; w < 32; w++) {
                int p  = tid + NTHREADS * w;
                int pi = p >> 6, pj = p & 63;
                float2 v = make_float2(staging[0][p], staging[1][p]);
                *(float2*)(out + ((size_t)(i0 + pi) * BYN + (j0 + pj)) * TN + tflush) = v;
            }
        }

        // ---- diff + transpose for step k+1 (reads rawN = rows s+2) ----
        if (more) {
#pragma unroll
            for (int q = 0; q < 16; q++) {
                float4 n = *(const float4*)&rawN[tid * PAD + q * 4];
                const int d0 = q * 4;
                dst[(d0 + 0) * PAD + r] = n.x - cur[q].x;
                dst[(d0 + 1) * PAD + r] = n.y - cur[q].y;
                dst[(d0 + 2) * PAD + r] = n.z - cur[q].z;
                dst[(d0 + 3) * PAD + r] = n.w - cur[q].w;
                cur[q] = n;
            }
        }
        __syncthreads();        // b2: dxs ready; rawN free for next cp.async
    }

    // chunk-total product
    float* Cp = g_Cprod + (size_t)blockIdx.y * (BXN * BYN);
#pragma unroll
    for (int a = 0; a < 8; a++) {
        float4 v = make_float4(K[a][0], K[a][1], K[a][2], K[a][3]);
        *(float4*)&Cp[(i0 + ty * 8 + a) * BYN + (j0 + tx * 4)] = v;
    }
}

// ---------------------------------------------------------------------------
__global__ void k2_prefix()
{
    const int p = blockIdx.x * blockDim.x + threadIdx.x;
    if (p >= BXN * BYN) return;
    float run = 1.0f;
#pragma unroll
    for (int c = 0; c < NC; c++) {
        const float v = g_Cprod[c * BXN * BYN + p];
        g_Pexc[c * BXN * BYN + p] = run;
        run *= v;
    }
}

// ---------------------------------------------------------------------------
__global__ void k3_scale(float* __restrict__ out)
{
    const size_t v = (size_t)blockIdx.x * blockDim.x + threadIdx.x;
    const size_t e = v * 4;
    const int pair = (int)(e >> 10);
    const int t    = (int)(e & (TN - 1));
    const int c    = t >> 4;             // CL == 16
    const float pf = g_Pexc[c * BXN * BYN + pair];
    float4 val = ((float4*)out)[v];
    val.x *= pf; val.y *= pf; val.z *= pf; val.w *= pf;
    ((float4*)out)[v] = val;
}

extern "C" void kernel_launch(void* const* d_in, const int* in_sizes, int n_in,
                              void* d_out, int out_size)
{
    const float* X = (const float*)d_in[0];
    const float* Y = (const float*)d_in[1];
    float* out = (float*)d_out;

    dim3 g1(4, NC);                      // 256 CTAs
    k1_chunk<<<g1, NTHREADS>>>(X, Y, out);

    k2_prefix<<<(BXN * BYN + 255) / 256, 256>>>();

    const int nvec = BXN * BYN * TN / 4;
    k3_scale<<<(nvec + 255) / 256, 256>>>(out);
}

// round 15
// speedup vs baseline: 1.5869x; 1.5869x over previous
#include <cuda_runtime.h>
#include <cuda_bf16.h>
#include <cstdint>

#define BXN 128
#define BYN 128
#define TN  1024
#define DN  64
#define NSTEPS 1023
#define CL  8
#define NC  128
#define NJT 64
#define NTH 256
#define RP  68
#define SP  72
#define NPAIR (BXN*BYN)

__device__ float g_Cprod[NC * NPAIR];
__device__ float g_Pexc [NC * NPAIR];
__device__ float g_scr  [(size_t)TN * NPAIR];   // t-major scratch (64MB)

#define SW(o) ((o) ^ (((o) >> 3) & 0x70))

struct __align__(1024) SmemL {
    __nv_bfloat16 xhi[128 * 64];   // SW128 K-major, 128B rows (16KB)
    __nv_bfloat16 xlo[128 * 64];
    __nv_bfloat16 yhi[64 * 64];    // 8KB
    __nv_bfloat16 ylo[64 * 64];
    float rawx[2][128 * RP];
    float rawy[2][64 * RP];
    float stg[128 * SP];           // staging [i][jlocal]
};

__device__ __forceinline__ void cp16(uint32_t dst, const float* src) {
    asm volatile("cp.async.ca.shared.global [%0], [%1], 16;\n" :: "r"(dst), "l"(src));
}
__device__ __forceinline__ void cp_commit() { asm volatile("cp.async.commit_group;\n"); }
__device__ __forceinline__ void cp_wait0()  { asm volatile("cp.async.wait_group 0;\n"); }

__device__ __forceinline__ void ldm_x4(uint32_t* r, uint32_t addr) {
    asm volatile("ldmatrix.sync.aligned.m8n8.x4.shared.b16 {%0,%1,%2,%3}, [%4];"
        : "=r"(r[0]), "=r"(r[1]), "=r"(r[2]), "=r"(r[3]) : "r"(addr));
}
__device__ __forceinline__ void mma16816(float* c, const uint32_t* a, const uint32_t* b) {
    asm volatile("mma.sync.aligned.m16n8k16.row.col.f32.bf16.bf16.f32 "
        "{%0,%1,%2,%3}, {%4,%5,%6,%7}, {%8,%9}, {%0,%1,%2,%3};"
        : "+f"(c[0]), "+f"(c[1]), "+f"(c[2]), "+f"(c[3])
        : "r"(a[0]), "r"(a[1]), "r"(a[2]), "r"(a[3]), "r"(b[0]), "r"(b[1]));
}

__device__ __forceinline__ void split_store(float4 a, float4 b,
                                            char* hi, char* lo, uint32_t sw) {
    float d0 = b.x - a.x, d1 = b.y - a.y, d2 = b.z - a.z, d3 = b.w - a.w;
    __nv_bfloat162 h01 = __floats2bfloat162_rn(d0, d1);
    __nv_bfloat162 h23 = __floats2bfloat162_rn(d2, d3);
    __nv_bfloat162 l01 = __floats2bfloat162_rn(d0 - __bfloat162float(h01.x),
                                               d1 - __bfloat162float(h01.y));
    __nv_bfloat162 l23 = __floats2bfloat162_rn(d2 - __bfloat162float(h23.x),
                                               d3 - __bfloat162float(h23.y));
    *(__nv_bfloat162*)(hi + sw)     = h01;
    *(__nv_bfloat162*)(hi + sw + 4) = h23;
    *(__nv_bfloat162*)(lo + sw)     = l01;
    *(__nv_bfloat162*)(lo + sw + 4) = l23;
}

// ---------------------------------------------------------------------------
// K1: mma.sync chunked scan. Grid (2, NC), 256 threads (8 warps).
// Warp w computes G stripe rows [16w,16w+16) x 64 j. bf16 hi/lo 4-term split
// reconstructs fp32 products exactly to ~2^-18.
// ---------------------------------------------------------------------------
__launch_bounds__(NTH, 1)
__global__ void k1_chunk(const float* __restrict__ X, const float* __restrict__ Y)
{
    extern __shared__ unsigned char smem_raw[];
    SmemL* s = (SmemL*)smem_raw;

    const int tid   = threadIdx.x;
    const int w     = tid >> 5;
    const int l     = tid & 31;
    const int j0    = blockIdx.x * NJT;
    const int c     = blockIdx.y;
    const int tbase = c * CL;
    const float STEP = 1.0f / 1023.0f;

    const int lr = tid >> 4;      // 0..15
    const int lq = tid & 15;      // d-quad

    const uint32_t rx[2] = { (uint32_t)__cvta_generic_to_shared(&s->rawx[0][0]),
                             (uint32_t)__cvta_generic_to_shared(&s->rawx[1][0]) };
    const uint32_t ry[2] = { (uint32_t)__cvta_generic_to_shared(&s->rawy[0][0]),
                             (uint32_t)__cvta_generic_to_shared(&s->rawy[1][0]) };

    auto load_slice = [&](int t, int buf) {
#pragma unroll
        for (int p = 0; p < 8; p++) {
            int r = lr + 16 * p;
            cp16(rx[buf] + (uint32_t)(r * RP + lq * 4) * 4u,
                 X + (size_t)r * TN * DN + (size_t)t * DN + lq * 4);
        }
#pragma unroll
        for (int p = 0; p < 4; p++) {
            int r = lr + 16 * p;
            cp16(ry[buf] + (uint32_t)(r * RP + lq * 4) * 4u,
                 Y + (size_t)(j0 + r) * TN * DN + (size_t)t * DN + lq * 4);
        }
        cp_commit();
    };

    load_slice(tbase, 0);
    load_slice(tbase + 1, 1);

    auto convert = [&](int k) {
        const int cb = k & 1, nb = cb ^ 1;
#pragma unroll
        for (int p = 0; p < 8; p++) {
            int r = lr + 16 * p;
            uint32_t sw = SW((uint32_t)(r * 128 + lq * 8));
            split_store(*(const float4*)&s->rawx[cb][r * RP + lq * 4],
                        *(const float4*)&s->rawx[nb][r * RP + lq * 4],
                        (char*)s->xhi, (char*)s->xlo, sw);
        }
#pragma unroll
        for (int p = 0; p < 4; p++) {
            int r = lr + 16 * p;
            uint32_t sw = SW((uint32_t)(r * 128 + lq * 8));
            split_store(*(const float4*)&s->rawy[cb][r * RP + lq * 4],
                        *(const float4*)&s->rawy[nb][r * RP + lq * 4],
                        (char*)s->yhi, (char*)s->ylo, sw);
        }
    };

    auto flush = [&](int t) {
        float* sc = g_scr + (size_t)t * NPAIR;
#pragma unroll
        for (int q = 0; q < 8; q++) {
            int g4  = tid + NTH * q;         // 0..2047
            int pi  = g4 >> 4;
            int pjq = g4 & 15;
            *(float4*)&sc[pi * BYN + j0 + pjq * 4] =
                *(const float4*)&s->stg[pi * SP + pjq * 4];
        }
    };

    const uint32_t xhiB = (uint32_t)__cvta_generic_to_shared(s->xhi);
    const uint32_t xloB = (uint32_t)__cvta_generic_to_shared(s->xlo);
    const uint32_t yhiB = (uint32_t)__cvta_generic_to_shared(s->yhi);
    const uint32_t yloB = (uint32_t)__cvta_generic_to_shared(s->ylo);

    // A-frag lane address pieces (row = w*16 + (l&15))
    const int arow = w * 16 + (l & 15);
    const int ach  = l >> 4;                 // 0/1: k-chunk parity
    // B-frag lane address pieces (row = n0 + (l&7))
    const int brow7 = l & 7;
    const int bch   = l >> 3;                // 0..3

    float K[8][4];
#pragma unroll
    for (int nt = 0; nt < 8; nt++)
#pragma unroll
        for (int q = 0; q < 4; q++) K[nt][q] = 1.0f;

#pragma unroll 1
    for (int k = 0; k < CL; k++) {
        const int s_ = tbase + k;

        __syncthreads();                     // staging(k-1) ready; tiles consumed
        if (k > 0) flush(tbase + k);

        if (s_ < NSTEPS) { cp_wait0(); convert(k); }
        __syncthreads();                     // tiles published

        if (s_ < NSTEPS) {
            if (s_ + 2 < TN) load_slice(s_ + 2, k & 1);

            const float t1  = (s_ + 1 == NSTEPS) ? 1.0f : (float)(s_ + 1) * STEP;
            const float t0  = (float)s_ * STEP;
            const float inv = 1.0f / (t1 - t0);

            // A fragments: 4 k-tiles, hi+lo
            uint32_t Ah[4][4], Al[4][4];
#pragma unroll
            for (int kt = 0; kt < 4; kt++) {
                uint32_t ch  = (uint32_t)(2 * kt + ach);
                uint32_t off = (uint32_t)(arow * 128) + ((ch ^ (uint32_t)(arow & 7)) << 4);
                ldm_x4(Ah[kt], xhiB + off);
                ldm_x4(Al[kt], xloB + off);
            }

#pragma unroll
            for (int nt = 0; nt < 8; nt++) {
                const int n0 = nt * 8;
                const int brow = n0 + brow7;
                uint32_t Bh[8], Bl[8];
                uint32_t o0 = (uint32_t)(brow * 128)
                            + (((uint32_t)bch ^ (uint32_t)(brow & 7)) << 4);
                uint32_t o1 = (uint32_t)(brow * 128)
                            + (((uint32_t)(4 + bch) ^ (uint32_t)(brow & 7)) << 4);
                ldm_x4(Bh,     yhiB + o0);
                ldm_x4(Bh + 4, yhiB + o1);
                ldm_x4(Bl,     yloB + o0);
                ldm_x4(Bl + 4, yloB + o1);

                float C0[4] = {0.f, 0.f, 0.f, 0.f};
                float C1[4] = {0.f, 0.f, 0.f, 0.f};
#pragma unroll
                for (int kt = 0; kt < 4; kt++) {
                    float* C = (kt & 1) ? C1 : C0;
                    mma16816(C, Ah[kt], Bh + 2 * kt);
                    mma16816(C, Ah[kt], Bl + 2 * kt);
                    mma16816(C, Al[kt], Bh + 2 * kt);
                    mma16816(C, Al[kt], Bl + 2 * kt);
                }
#pragma unroll
                for (int q = 0; q < 4; q++)
                    K[nt][q] *= fmaf(C0[q] + C1[q], inv, 1.0f);

                // staging write: rows w*16+(l>>2) and +8, cols n0+(l&3)*2
                const int ia = w * 16 + (l >> 2);
                const int jj = n0 + (l & 3) * 2;
                *(float2*)&s->stg[ia * SP + jj]       = make_float2(K[nt][0], K[nt][1]);
                *(float2*)&s->stg[(ia + 8) * SP + jj] = make_float2(K[nt][2], K[nt][3]);
            }
        }
    }

    __syncthreads();
    if (tbase + CL - 1 < NSTEPS) flush(tbase + CL);

    // chunk-total product = last staged K (coalesced from staging)
    {
        float* Cp = g_Cprod + (size_t)c * NPAIR;
#pragma unroll
        for (int q = 0; q < 8; q++) {
            int g4  = tid + NTH * q;
            int pi  = g4 >> 4;
            int pjq = g4 & 15;
            *(float4*)&Cp[pi * BYN + j0 + pjq * 4] =
                *(const float4*)&s->stg[pi * SP + pjq * 4];
        }
    }
}

// ---------------------------------------------------------------------------
__global__ void k2_prefix()
{
    const int p = blockIdx.x * blockDim.x + threadIdx.x;
    if (p >= NPAIR) return;
    float run = 1.0f;
#pragma unroll 8
    for (int c = 0; c < NC; c++) {
        const float v = g_Cprod[c * NPAIR + p];
        g_Pexc[c * NPAIR + p] = run;
        run *= v;
    }
}

// ---------------------------------------------------------------------------
// K3: scratch (t-major) -> out (pair-major) via smem transpose + chunk prefix.
// ---------------------------------------------------------------------------
__launch_bounds__(256)
__global__ void k3_transpose(float* __restrict__ out)
{
    __shared__ float tileS[64][65];
    __shared__ float pexS[9][64];
    const int t0 = blockIdx.x * 64;
    const int p0 = blockIdx.y * 64;
    const int tid = threadIdx.x;
    const int cbase = (t0 == 0) ? 0 : ((t0 - 1) >> 3);

    for (int idx = tid; idx < 9 * 64; idx += 256) {
        int cc = cbase + (idx >> 6);
        int pp = idx & 63;
        pexS[idx >> 6][pp] = (cc < NC) ? g_Pexc[cc * NPAIR + p0 + pp] : 1.0f;
    }
    const int tr = tid >> 6;   // 0..3
    const int tc = tid & 63;
#pragma unroll
    for (int rr = 0; rr < 16; rr++) {
        int r = rr * 4 + tr;
        tileS[r][tc] = g_scr[(size_t)(t0 + r) * NPAIR + p0 + tc];
    }
    __syncthreads();
#pragma unroll
    for (int pp = 0; pp < 16; pp++) {
        int pl = pp * 4 + tr;
        int t  = t0 + tc;
        float v;
        if (t == 0) v = 1.0f;
        else        v = tileS[tc][pl] * pexS[((t - 1) >> 3) - cbase][pl];
        out[(size_t)(p0 + pl) * TN + t] = v;
    }
}

extern "C" void kernel_launch(void* const* d_in, const int* in_sizes, int n_in,
                              void* d_out, int out_size)
{
    const float* X = (const float*)d_in[0];
    const float* Y = (const float*)d_in[1];
    float* out = (float*)d_out;

    const int smem_sz = (int)sizeof(SmemL);
    cudaFuncSetAttribute(k1_chunk, cudaFuncAttributeMaxDynamicSharedMemorySize, smem_sz);

    k1_chunk<<<dim3(2, NC), NTH, smem_sz>>>(X, Y);
    k2_prefix<<<(NPAIR + 255) / 256, 256>>>();
    k3_transpose<<<dim3(TN / 64, NPAIR / 64), 256>>>(out);
}

// round 16
// speedup vs baseline: 2.0085x; 1.2657x over previous
#include <cuda_runtime.h>
#include <cuda_bf16.h>
#include <cstdint>

#define BXN 128
#define BYN 128
#define TN  1024
#define DN  64
#define NSTEPS 1023
#define CL  14
#define NC  74        // 74*14 = 1036 >= 1023; last chunk clamps
#define NJT 64
#define NTH 512
#define RP  68
#define SP  72
#define NPAIR (BXN*BYN)

__device__ float g_Cprod[NC * NPAIR];
__device__ float g_Pexc [NC * NPAIR];
__device__ float g_scr  [(size_t)TN * NPAIR];   // t-major scratch (64MB)

#define SW(o) ((o) ^ (((o) >> 3) & 0x70))

struct __align__(1024) SmemL {
    __nv_bfloat16 xhi[128 * 64];   // SW128 K-major (16KB)
    __nv_bfloat16 xlo[128 * 64];
    __nv_bfloat16 yhi[64 * 64];    // 8KB
    __nv_bfloat16 ylo[64 * 64];
    float rawx[2][128 * RP];
    float rawy[2][64 * RP];
    float stg[128 * SP];
};

__device__ __forceinline__ void cp16(uint32_t dst, const float* src) {
    asm volatile("cp.async.ca.shared.global [%0], [%1], 16;\n" :: "r"(dst), "l"(src));
}
__device__ __forceinline__ void cp_commit() { asm volatile("cp.async.commit_group;\n"); }
__device__ __forceinline__ void cp_wait0()  { asm volatile("cp.async.wait_group 0;\n"); }

__device__ __forceinline__ void ldm_x4(uint32_t* r, uint32_t addr) {
    asm volatile("ldmatrix.sync.aligned.m8n8.x4.shared.b16 {%0,%1,%2,%3}, [%4];"
        : "=r"(r[0]), "=r"(r[1]), "=r"(r[2]), "=r"(r[3]) : "r"(addr));
}
__device__ __forceinline__ void mma16816(float* c, const uint32_t* a, const uint32_t* b) {
    asm volatile("mma.sync.aligned.m16n8k16.row.col.f32.bf16.bf16.f32 "
        "{%0,%1,%2,%3}, {%4,%5,%6,%7}, {%8,%9}, {%0,%1,%2,%3};"
        : "+f"(c[0]), "+f"(c[1]), "+f"(c[2]), "+f"(c[3])
        : "r"(a[0]), "r"(a[1]), "r"(a[2]), "r"(a[3]), "r"(b[0]), "r"(b[1]));
}

__device__ __forceinline__ void split_store(float4 a, float4 b,
                                            char* hi, char* lo, uint32_t sw) {
    float d0 = b.x - a.x, d1 = b.y - a.y, d2 = b.z - a.z, d3 = b.w - a.w;
    __nv_bfloat162 h01 = __floats2bfloat162_rn(d0, d1);
    __nv_bfloat162 h23 = __floats2bfloat162_rn(d2, d3);
    __nv_bfloat162 l01 = __floats2bfloat162_rn(d0 - __bfloat162float(h01.x),
                                               d1 - __bfloat162float(h01.y));
    __nv_bfloat162 l23 = __floats2bfloat162_rn(d2 - __bfloat162float(h23.x),
                                               d3 - __bfloat162float(h23.y));
    *(__nv_bfloat162*)(hi + sw)     = h01;
    *(__nv_bfloat162*)(hi + sw + 4) = h23;
    *(__nv_bfloat162*)(lo + sw)     = l01;
    *(__nv_bfloat162*)(lo + sw + 4) = l23;
}

// ---------------------------------------------------------------------------
// K1: mma.sync chunked scan. Grid (2, 74) = 148 CTAs (one wave), 512 threads
// (16 warps -> 4/SMSP). Warp (wi = w&7, wj = w>>3) computes the 16x32 stripe
// rows [16wi,16wi+16) x cols [32wj,32wj+32). 3-term bf16 hi/lo split
// (hh + hl + lh; ll ~ 2^-18 dropped).
// ---------------------------------------------------------------------------
__launch_bounds__(NTH, 1)
__global__ void k1_chunk(const float* __restrict__ X, const float* __restrict__ Y)
{
    extern __shared__ unsigned char smem_raw[];
    SmemL* s = (SmemL*)smem_raw;

    const int tid   = threadIdx.x;
    const int w     = tid >> 5;
    const int l     = tid & 31;
    const int wi    = w & 7;
    const int wj    = w >> 3;
    const int j0    = blockIdx.x * NJT;
    const int c     = blockIdx.y;
    const int tbase = c * CL;
    const float STEP = 1.0f / 1023.0f;

    const uint32_t rx[2] = { (uint32_t)__cvta_generic_to_shared(&s->rawx[0][0]),
                             (uint32_t)__cvta_generic_to_shared(&s->rawx[1][0]) };
    const uint32_t ry[2] = { (uint32_t)__cvta_generic_to_shared(&s->rawy[0][0]),
                             (uint32_t)__cvta_generic_to_shared(&s->rawy[1][0]) };

    auto load_slice = [&](int t, int buf) {
#pragma unroll
        for (int p = 0; p < 4; p++) {
            int idx = tid + NTH * p;            // 2048 X quads
            int r = idx >> 4, lq = idx & 15;
            cp16(rx[buf] + (uint32_t)(r * RP + lq * 4) * 4u,
                 X + (size_t)r * TN * DN + (size_t)t * DN + lq * 4);
        }
#pragma unroll
        for (int p = 0; p < 2; p++) {
            int idx = tid + NTH * p;            // 1024 Y quads
            int r = idx >> 4, lq = idx & 15;
            cp16(ry[buf] + (uint32_t)(r * RP + lq * 4) * 4u,
                 Y + (size_t)(j0 + r) * TN * DN + (size_t)t * DN + lq * 4);
        }
        cp_commit();
    };

    load_slice(tbase, 0);
    load_slice(tbase + 1, 1);

    auto convert = [&](int k) {
        const int cb = k & 1, nb = cb ^ 1;
#pragma unroll
        for (int p = 0; p < 4; p++) {
            int idx = tid + NTH * p;
            int r = idx >> 4, lq = idx & 15;
            uint32_t sw = SW((uint32_t)(r * 128 + lq * 8));
            split_store(*(const float4*)&s->rawx[cb][r * RP + lq * 4],
                        *(const float4*)&s->rawx[nb][r * RP + lq * 4],
                        (char*)s->xhi, (char*)s->xlo, sw);
        }
#pragma unroll
        for (int p = 0; p < 2; p++) {
            int idx = tid + NTH * p;
            int r = idx >> 4, lq = idx & 15;
            uint32_t sw = SW((uint32_t)(r * 128 + lq * 8));
            split_store(*(const float4*)&s->rawy[cb][r * RP + lq * 4],
                        *(const float4*)&s->rawy[nb][r * RP + lq * 4],
                        (char*)s->yhi, (char*)s->ylo, sw);
        }
    };

    auto flush = [&](int t) {
        float* sc = g_scr + (size_t)t * NPAIR;
#pragma unroll
        for (int p = 0; p < 4; p++) {
            int g4  = tid + NTH * p;            // 2048 float4s
            int pi  = g4 >> 4;
            int pjq = g4 & 15;
            *(float4*)&sc[pi * BYN + j0 + pjq * 4] =
                *(const float4*)&s->stg[pi * SP + pjq * 4];
        }
    };

    const uint32_t xhiB = (uint32_t)__cvta_generic_to_shared(s->xhi);
    const uint32_t xloB = (uint32_t)__cvta_generic_to_shared(s->xlo);
    const uint32_t yhiB = (uint32_t)__cvta_generic_to_shared(s->yhi);
    const uint32_t yloB = (uint32_t)__cvta_generic_to_shared(s->ylo);

    const int arow  = wi * 16 + (l & 15);
    const int ach   = l >> 4;
    const int brow7 = l & 7;
    const int bch   = l >> 3;

    float K[4][4];
#pragma unroll
    for (int nt = 0; nt < 4; nt++)
#pragma unroll
        for (int q = 0; q < 4; q++) K[nt][q] = 1.0f;

#pragma unroll 1
    for (int k = 0; k < CL; k++) {
        const int s_ = tbase + k;

        __syncthreads();                        // staging(k-1) ready; tiles consumed
        if (k > 0 && tbase + k <= NSTEPS) flush(tbase + k);

        if (s_ < NSTEPS) { cp_wait0(); convert(k); }
        __syncthreads();                        // tiles published

        if (s_ < NSTEPS) {
            if (s_ + 2 < TN) load_slice(s_ + 2, k & 1);

            const float t1  = (s_ + 1 == NSTEPS) ? 1.0f : (float)(s_ + 1) * STEP;
            const float t0  = (float)s_ * STEP;
            const float inv = 1.0f / (t1 - t0);

            uint32_t Ah[4][4], Al[4][4];
#pragma unroll
            for (int kt = 0; kt < 4; kt++) {
                uint32_t ch  = (uint32_t)(2 * kt + ach);
                uint32_t off = (uint32_t)(arow * 128) + ((ch ^ (uint32_t)(arow & 7)) << 4);
                ldm_x4(Ah[kt], xhiB + off);
                ldm_x4(Al[kt], xloB + off);
            }

#pragma unroll
            for (int nt = 0; nt < 4; nt++) {
                const int n0   = wj * 32 + nt * 8;
                const int brow = n0 + brow7;
                uint32_t Bh[8], Bl[8];
                uint32_t o0 = (uint32_t)(brow * 128)
                            + (((uint32_t)bch ^ (uint32_t)(brow & 7)) << 4);
                uint32_t o1 = (uint32_t)(brow * 128)
                            + (((uint32_t)(4 + bch) ^ (uint32_t)(brow & 7)) << 4);
                ldm_x4(Bh,     yhiB + o0);
                ldm_x4(Bh + 4, yhiB + o1);
                ldm_x4(Bl,     yloB + o0);
                ldm_x4(Bl + 4, yloB + o1);

                float C0[4] = {0.f, 0.f, 0.f, 0.f};
                float C1[4] = {0.f, 0.f, 0.f, 0.f};
#pragma unroll
                for (int kt = 0; kt < 4; kt++) {
                    float* C = (kt & 1) ? C1 : C0;
                    mma16816(C, Ah[kt], Bh + 2 * kt);   // hh
                    mma16816(C, Ah[kt], Bl + 2 * kt);   // hl
                    mma16816(C, Al[kt], Bh + 2 * kt);   // lh
                }
#pragma unroll
                for (int q = 0; q < 4; q++)
                    K[nt][q] *= fmaf(C0[q] + C1[q], inv, 1.0f);

                const int ia = wi * 16 + (l >> 2);
                const int jj = n0 + (l & 3) * 2;
                *(float2*)&s->stg[ia * SP + jj]       = make_float2(K[nt][0], K[nt][1]);
                *(float2*)&s->stg[(ia + 8) * SP + jj] = make_float2(K[nt][2], K[nt][3]);
            }
        }
    }

    __syncthreads();
    if (tbase + CL <= NSTEPS) flush(tbase + CL);

    // chunk-total product (coalesced from staging)
    {
        float* Cp = g_Cprod + (size_t)c * NPAIR;
#pragma unroll
        for (int p = 0; p < 4; p++) {
            int g4  = tid + NTH * p;
            int pi  = g4 >> 4;
            int pjq = g4 & 15;
            *(float4*)&Cp[pi * BYN + j0 + pjq * 4] =
                *(const float4*)&s->stg[pi * SP + pjq * 4];
        }
    }
}

// ---------------------------------------------------------------------------
__global__ void k2_prefix()
{
    const int p = blockIdx.x * blockDim.x + threadIdx.x;
    if (p >= NPAIR) return;
    float run = 1.0f;
#pragma unroll 2
    for (int c = 0; c < NC; c++) {
        const float v = g_Cprod[c * NPAIR + p];
        g_Pexc[c * NPAIR + p] = run;
        run *= v;
    }
}

// ---------------------------------------------------------------------------
// K3: scratch (t-major) -> out (pair-major) via smem transpose + chunk prefix.
// ---------------------------------------------------------------------------
__launch_bounds__(256)
__global__ void k3_transpose(float* __restrict__ out)
{
    __shared__ float tileS[64][65];
    __shared__ float pexS[6][64];
    const int t0 = blockIdx.x * 64;
    const int p0 = blockIdx.y * 64;
    const int tid = threadIdx.x;
    const int cbase = (t0 == 0) ? 0 : ((t0 - 1) / CL);

    for (int idx = tid; idx < 6 * 64; idx += 256) {
        int cc = cbase + (idx >> 6);
        int pp = idx & 63;
        pexS[idx >> 6][pp] = (cc < NC) ? g_Pexc[cc * NPAIR + p0 + pp] : 1.0f;
    }
    const int tr = tid >> 6;   // 0..3
    const int tc = tid & 63;
#pragma unroll
    for (int rr = 0; rr < 16; rr++) {
        int r = rr * 4 + tr;
        tileS[r][tc] = g_scr[(size_t)(t0 + r) * NPAIR + p0 + tc];
    }
    __syncthreads();
#pragma unroll
    for (int pp = 0; pp < 16; pp++) {
        int pl = pp * 4 + tr;
        int t  = t0 + tc;
        float v;
        if (t == 0) v = 1.0f;
        else        v = tileS[tc][pl] * pexS[((t - 1) / CL) - cbase][pl];
        out[(size_t)(p0 + pl) * TN + t] = v;
    }
}

extern "C" void kernel_launch(void* const* d_in, const int* in_sizes, int n_in,
                              void* d_out, int out_size)
{
    const float* X = (const float*)d_in[0];
    const float* Y = (const float*)d_in[1];
    float* out = (float*)d_out;

    const int smem_sz = (int)sizeof(SmemL);
    cudaFuncSetAttribute(k1_chunk, cudaFuncAttributeMaxDynamicSharedMemorySize, smem_sz);

    k1_chunk<<<dim3(2, NC), NTH, smem_sz>>>(X, Y);
    k2_prefix<<<(NPAIR + 255) / 256, 256>>>();
    k3_transpose<<<dim3(TN / 64, NPAIR / 64), 256>>>(out);
}